// round 16
// baseline (speedup 1.0000x reference)
#include <cuda_runtime.h>
#include <cuda_bf16.h>
#include <cstdint>

#define BB 8
#define NN 1024
#define HH 32
#define BN (BB*NN)
#define NT 32
#define NTILES 32                      // NN/NT
#define NPAIRT 528                     // NTILES*(NTILES+1)/2

#define UPITCH 33                      // u tiles (f32): conflict-free row reads
#define QPITCH 40                      // q tiles (bf16): 80B rows -> conflict-free frag LDS.32
#define WPITCH 40                      // packed W tiles (u32 rows)

__device__ float g_part[BB * NTILES * NN];     // [b][other_tile][node] partials

__device__ __forceinline__ float lrelu(float v) { return fmaxf(v, 0.01f * v); }

// D += A(bf16) * B(bf16), m16n8k16, fp32 accumulate (baseline sm_80+ — no 'a' gating)
#define MMA_BF16(d0,d1,d2,d3, a0,a1,a2,a3, b0,b1)                                   \
    asm volatile("mma.sync.aligned.m16n8k16.row.col.f32.bf16.bf16.f32 "             \
                 "{%0,%1,%2,%3}, {%4,%5,%6,%7}, {%8,%9}, {%0,%1,%2,%3};"            \
                 : "+f"(d0), "+f"(d1), "+f"(d2), "+f"(d3)                           \
                 : "r"(a0), "r"(a1), "r"(a2), "r"(a3), "r"(b0), "r"(b1))

// ---------------------------------------------------------------------------
// Kernel 1: symmetric tiled pair-MLP; layer 2 on tensor pipe (bf16 HMMA x3).
// Block = (b, tile-pair ti<=tj); 4 warps; warp w does rows r = c*4+w.
// Per warp-chunk: M=32 pairs x N=32 l x K=32 GEMM = 2m x 4n x 2kt m16n8k16 x3.
// u precompute fused into prologue (no separate kernel, no g_u).
// ---------------------------------------------------------------------------
__global__ __launch_bounds__(128, 4) void mpnn_pairs(
    const float* __restrict__ x,   const float* __restrict__ A,
    const float* __restrict__ Wm1, const float* __restrict__ bm1,
    const float* __restrict__ Wm2, const float* __restrict__ bm2,
    const float* __restrict__ Wm3, const float* __restrict__ bm3)
{
    __shared__ float          uti[NT * UPITCH];        // u_i tile [r][h]
    __shared__ float          utj[NT * UPITCH];        // u_j tile [jj][h]
    __shared__ __nv_bfloat16  qhi_s[4][NT * QPITCH];   // per-warp q hi [pair][k]
    __shared__ __nv_bfloat16  qlo_s[4][NT * QPITCH];   // per-warp q lo
    __shared__ uint32_t       whiP[16 * WPITCH];       // W2 hi packed {W[2k2],W[2k2+1]} [k2][l]
    __shared__ uint32_t       wloP[16 * WPITCH];       // W2 lo packed
    __shared__ float          b2s[HH], w3s[HH];
    __shared__ float          csh[4][NT];

    const int blk = blockIdx.x;
    const int b   = blk / NPAIRT;
    int tt = blk % NPAIRT;
    int ti = 0;
    while (tt >= NTILES - ti) { tt -= NTILES - ti; ++ti; }
    const int tj = ti + tt;
    const bool diag = (ti == tj);

    const int tid  = threadIdx.x;
    const int lane = tid & 31;
    const int wrp  = tid >> 5;
    const int grp  = lane >> 2;        // 0..7
    const int tg   = lane & 3;         // 0..3
    const int i0   = ti * NT;
    const int j0   = tj * NT;

    // ---- prologue A: fused u precompute straight into smem tiles ----
    #pragma unroll 1
    for (int idx = tid; idx < 2 * NT * HH; idx += 128) {
        int half = idx >> 10;                  // 0 = i-tile, 1 = j-tile
        int rest = idx & 1023;
        int nl = rest >> 5, h = rest & 31;
        int node = (half ? j0 : i0) + nl;
        float rho = x[((size_t)b * NN + node) * 2 + 0];
        float V   = x[((size_t)b * NN + node) * 2 + 1];
        float uv  = rho * Wm1[h] + V * Wm1[HH + h] + 0.5f * bm1[h];
        if (half) utj[nl * UPITCH + h] = uv; else uti[nl * UPITCH + h] = uv;
    }

    // ---- prologue B: W2 as packed bf16 hi/lo, pairs along k ----
    #pragma unroll 1
    for (int idx = tid; idx < 16 * HH; idx += 128) {
        int k2 = idx >> 5, l = idx & 31;
        float w0 = Wm2[(2 * k2) * HH + l];
        float w1 = Wm2[(2 * k2 + 1) * HH + l];
        __nv_bfloat162 h2, l2;
        h2.x = __float2bfloat16_rn(w0);
        h2.y = __float2bfloat16_rn(w1);
        l2.x = __float2bfloat16_rn(w0 - __bfloat162float(h2.x));
        l2.y = __float2bfloat16_rn(w1 - __bfloat162float(h2.y));
        whiP[k2 * WPITCH + l] = *reinterpret_cast<uint32_t*>(&h2);
        wloP[k2 * WPITCH + l] = *reinterpret_cast<uint32_t*>(&l2);
    }
    if (tid < HH) { b2s[tid] = bm2[tid]; w3s[tid] = Wm3[tid]; }
    __syncthreads();

    // ---- hoist B-fragments into registers (loop-invariant across chunks) ----
    uint32_t BH[2][4][2], BL[2][4][2];
    #pragma unroll
    for (int kt = 0; kt < 2; ++kt)
        #pragma unroll
        for (int n = 0; n < 4; ++n) {
            BH[kt][n][0] = whiP[(8*kt + tg)     * WPITCH + 8*n + grp];
            BH[kt][n][1] = whiP[(8*kt + tg + 4) * WPITCH + 8*n + grp];
            BL[kt][n][0] = wloP[(8*kt + tg)     * WPITCH + 8*n + grp];
            BL[kt][n][1] = wloP[(8*kt + tg + 4) * WPITCH + 8*n + grp];
        }

    const float bm3v = bm3[0];
    __nv_bfloat16* qh = qhi_s[wrp];
    __nv_bfloat16* ql = qlo_s[wrp];
    const char* qh_c = (const char*)qh;
    const char* ql_c = (const char*)ql;
    float colacc[4] = {0.f, 0.f, 0.f, 0.f};

    #pragma unroll 1
    for (int c = 0; c < 8; ++c) {
        const int r = (c << 2) + wrp;

        // ---- phase 1: q = lrelu(u_i[r][k] + u_j[jj][k]); split bf16 hi/lo ----
        const float uir = uti[r * UPITCH + lane];      // lane = k
        #pragma unroll 4
        for (int jj = 0; jj < NT; ++jj) {
            float q = lrelu(uir + utj[jj * UPITCH + lane]);
            __nv_bfloat16 h = __float2bfloat16_rn(q);
            __nv_bfloat16 lo = __float2bfloat16_rn(q - __bfloat162float(h));
            qh[jj * QPITCH + lane] = h;                // STS.16, word-merged
            ql[jj * QPITCH + lane] = lo;
        }
        __syncwarp();

        // ---- phase 2: bf16x3 HMMA ----
        float d[2][4][4];
        #pragma unroll
        for (int m = 0; m < 2; ++m)
            #pragma unroll
            for (int n = 0; n < 4; ++n)
                #pragma unroll
                for (int e = 0; e < 4; ++e) d[m][n][e] = 0.f;

        #pragma unroll
        for (int kt = 0; kt < 2; ++kt) {
            uint32_t ah[2][4], al[2][4];
            #pragma unroll
            for (int m = 0; m < 2; ++m) {
                // byte offsets: row*(QPITCH*2) + kt*32 + tg*4 (+16 for k+8 group)
                int r0 = (16*m + grp) * (QPITCH * 2) + kt * 32 + tg * 4;
                int r1 = (16*m + grp + 8) * (QPITCH * 2) + kt * 32 + tg * 4;
                ah[m][0] = *(const uint32_t*)(qh_c + r0);
                ah[m][1] = *(const uint32_t*)(qh_c + r1);
                ah[m][2] = *(const uint32_t*)(qh_c + r0 + 16);
                ah[m][3] = *(const uint32_t*)(qh_c + r1 + 16);
                al[m][0] = *(const uint32_t*)(ql_c + r0);
                al[m][1] = *(const uint32_t*)(ql_c + r1);
                al[m][2] = *(const uint32_t*)(ql_c + r0 + 16);
                al[m][3] = *(const uint32_t*)(ql_c + r1 + 16);
            }
            #pragma unroll
            for (int n = 0; n < 4; ++n)
                #pragma unroll
                for (int m = 0; m < 2; ++m) {
                    MMA_BF16(d[m][n][0], d[m][n][1], d[m][n][2], d[m][n][3],
                             ah[m][0], ah[m][1], ah[m][2], ah[m][3],
                             BH[kt][n][0], BH[kt][n][1]);
                    MMA_BF16(d[m][n][0], d[m][n][1], d[m][n][2], d[m][n][3],
                             ah[m][0], ah[m][1], ah[m][2], ah[m][3],
                             BL[kt][n][0], BL[kt][n][1]);
                    MMA_BF16(d[m][n][0], d[m][n][1], d[m][n][2], d[m][n][3],
                             al[m][0], al[m][1], al[m][2], al[m][3],
                             BH[kt][n][0], BH[kt][n][1]);
                }
        }

        // ---- epilogue: thread owns pairs jj = grp + 8t; cols l = 8n + 2tg(+1) ----
        float me[4];
        #pragma unroll
        for (int t = 0; t < 4; ++t) {
            const int m  = t >> 1;
            const int o0 = (t & 1) << 1;
            float s = 0.f;
            #pragma unroll
            for (int n = 0; n < 4; ++n) {
                int l0 = 8*n + 2*tg;
                s += lrelu(d[m][n][o0]     + b2s[l0])     * w3s[l0];
                s += lrelu(d[m][n][o0 + 1] + b2s[l0 + 1]) * w3s[l0 + 1];
            }
            s += __shfl_xor_sync(0xffffffffu, s, 1);
            s += __shfl_xor_sync(0xffffffffu, s, 2);
            me[t] = tanhf(s + bm3v);
        }

        // ---- row credit ----
        float tr = 0.f;
        if (tg == 0) {
            #pragma unroll
            for (int t = 0; t < 4; ++t)
                tr += A[(size_t)(i0 + r) * NN + j0 + grp + 8*t] * me[t];
        }
        tr += __shfl_xor_sync(0xffffffffu, tr, 1);
        tr += __shfl_xor_sync(0xffffffffu, tr, 2);
        tr += __shfl_xor_sync(0xffffffffu, tr, 4);
        tr += __shfl_xor_sync(0xffffffffu, tr, 8);
        tr += __shfl_xor_sync(0xffffffffu, tr, 16);
        if (lane == 0)
            g_part[(size_t)(b * NTILES + tj) * NN + i0 + r] = tr;

        // ---- col credit (off-diag) ----
        if (!diag) {
            #pragma unroll
            for (int t = 0; t < 4; ++t)
                colacc[t] += A[(size_t)(j0 + grp + 8*t) * NN + i0 + r] * me[t];
        }
        __syncwarp();
    }

    if (!diag) {
        if (tg == 0) {
            #pragma unroll
            for (int t = 0; t < 4; ++t) csh[wrp][grp + 8*t] = colacc[t];
        }
        __syncthreads();
        if (wrp == 0) {
            float cv = csh[0][lane] + csh[1][lane] + csh[2][lane] + csh[3][lane];
            g_part[(size_t)(b * NTILES + ti) * NN + j0 + lane] = cv;
        }
    }
}

// ---------------------------------------------------------------------------
// Kernel 2: finalize — sum 32 partials per node, node MLP.
// ---------------------------------------------------------------------------
__global__ __launch_bounds__(128) void mpnn_finalize(
    const float* __restrict__ x,
    const float* __restrict__ Wx1, const float* __restrict__ bx1,
    const float* __restrict__ Wx2, const float* __restrict__ bx2,
    const float* __restrict__ Wx3, const float* __restrict__ bx3,
    float* __restrict__ out)
{
    __shared__ float hsh[4][HH];
    const int lane = threadIdx.x & 31;
    const int wrp  = threadIdx.x >> 5;
    const int node = blockIdx.x * 4 + wrp;
    const int b    = node >> 10;
    const int i    = node & (NN - 1);

    float ps = g_part[(size_t)(b * NTILES + lane) * NN + i];
    #pragma unroll
    for (int off = 16; off; off >>= 1) ps += __shfl_xor_sync(0xffffffffu, ps, off);
    const float msum = ps;

    const float rho = x[node * 2 + 0];
    float h1b = lrelu(rho * Wx1[lane] + msum * Wx1[HH + lane] + bx1[lane]);
    hsh[wrp][lane] = h1b;
    __syncwarp();

    float h2b = bx2[lane];
    #pragma unroll
    for (int k = 0; k < HH; ++k) h2b += Wx2[k * HH + lane] * hsh[wrp][k];

    float v = lrelu(h2b) * Wx3[lane];
    #pragma unroll
    for (int off = 16; off; off >>= 1) v += __shfl_xor_sync(0xffffffffu, v, off);

    if (lane == 0) out[node] = tanhf(v + bx3[0]);
}

// ---------------------------------------------------------------------------
extern "C" void kernel_launch(void* const* d_in, const int* in_sizes, int n_in,
                              void* d_out, int out_size) {
    const float* x   = (const float*)d_in[0];
    const float* A   = (const float*)d_in[1];
    const float* Wm1 = (const float*)d_in[2];
    const float* bm1 = (const float*)d_in[3];
    const float* Wm2 = (const float*)d_in[4];
    const float* bm2 = (const float*)d_in[5];
    const float* Wm3 = (const float*)d_in[6];
    const float* bm3 = (const float*)d_in[7];
    const float* Wx1 = (const float*)d_in[8];
    const float* bx1 = (const float*)d_in[9];
    const float* Wx2 = (const float*)d_in[10];
    const float* bx2 = (const float*)d_in[11];
    const float* Wx3 = (const float*)d_in[12];
    const float* bx3 = (const float*)d_in[13];
    float* out = (float*)d_out;

    mpnn_pairs<<<BB * NPAIRT, 128>>>(x, A, Wm1, bm1, Wm2, bm2, Wm3, bm3);
    mpnn_finalize<<<BN / 4, 128>>>(x, Wx1, bx1, Wx2, bx2, Wx3, bx3, out);
}

// round 17
// speedup vs baseline: 1.0002x; 1.0002x over previous
#include <cuda_runtime.h>
#include <cuda_bf16.h>
#include <cstdint>

#define BB 8
#define NN 1024
#define HH 32
#define BN (BB*NN)
#define NT 32
#define NTILES 32                      // NN/NT
#define NPAIRT 528                     // NTILES*(NTILES+1)/2

#define UPITCH 33                      // u tiles (f32): conflict-free row reads
#define QPITCH 40                      // q tiles (bf16): 80B rows -> conflict-free frag LDS.32
#define WPITCH 40                      // packed W tiles (u32 rows)

__device__ float g_part[BB * NTILES * NN];     // [b][other_tile][node] partials

__device__ __forceinline__ float lrelu(float v) { return fmaxf(v, 0.01f * v); }

// D += A(bf16) * B(bf16), m16n8k16, fp32 accumulate (baseline sm_80+ — no 'a' gating)
#define MMA_BF16(d0,d1,d2,d3, a0,a1,a2,a3, b0,b1)                                   \
    asm volatile("mma.sync.aligned.m16n8k16.row.col.f32.bf16.bf16.f32 "             \
                 "{%0,%1,%2,%3}, {%4,%5,%6,%7}, {%8,%9}, {%0,%1,%2,%3};"            \
                 : "+f"(d0), "+f"(d1), "+f"(d2), "+f"(d3)                           \
                 : "r"(a0), "r"(a1), "r"(a2), "r"(a3), "r"(b0), "r"(b1))

// ---------------------------------------------------------------------------
// Kernel 1: symmetric tiled pair-MLP; layer 2 on tensor pipe (bf16 HMMA x3).
// Block = (b, tile-pair ti<=tj); 4 warps; warp w does rows r = c*4+w.
// Per warp-chunk: M=32 pairs x N=32 l x K=32 GEMM = 2m x 4n x 2kt m16n8k16 x3.
// u precompute fused into prologue (no separate kernel, no g_u).
// ---------------------------------------------------------------------------
__global__ __launch_bounds__(128, 4) void mpnn_pairs(
    const float* __restrict__ x,   const float* __restrict__ A,
    const float* __restrict__ Wm1, const float* __restrict__ bm1,
    const float* __restrict__ Wm2, const float* __restrict__ bm2,
    const float* __restrict__ Wm3, const float* __restrict__ bm3)
{
    __shared__ float          uti[NT * UPITCH];        // u_i tile [r][h]
    __shared__ float          utj[NT * UPITCH];        // u_j tile [jj][h]
    __shared__ __nv_bfloat16  qhi_s[4][NT * QPITCH];   // per-warp q hi [pair][k]
    __shared__ __nv_bfloat16  qlo_s[4][NT * QPITCH];   // per-warp q lo
    __shared__ uint32_t       whiP[16 * WPITCH];       // W2 hi packed {W[2k2],W[2k2+1]} [k2][l]
    __shared__ uint32_t       wloP[16 * WPITCH];       // W2 lo packed
    __shared__ float          b2s[HH], w3s[HH];
    __shared__ float          csh[4][NT];

    const int blk = blockIdx.x;
    const int b   = blk / NPAIRT;
    int tt = blk % NPAIRT;
    int ti = 0;
    while (tt >= NTILES - ti) { tt -= NTILES - ti; ++ti; }
    const int tj = ti + tt;
    const bool diag = (ti == tj);

    const int tid  = threadIdx.x;
    const int lane = tid & 31;
    const int wrp  = tid >> 5;
    const int grp  = lane >> 2;        // 0..7
    const int tg   = lane & 3;         // 0..3
    const int i0   = ti * NT;
    const int j0   = tj * NT;

    // ---- prologue A: fused u precompute straight into smem tiles ----
    #pragma unroll 1
    for (int idx = tid; idx < 2 * NT * HH; idx += 128) {
        int half = idx >> 10;                  // 0 = i-tile, 1 = j-tile
        int rest = idx & 1023;
        int nl = rest >> 5, h = rest & 31;
        int node = (half ? j0 : i0) + nl;
        float rho = x[((size_t)b * NN + node) * 2 + 0];
        float V   = x[((size_t)b * NN + node) * 2 + 1];
        float uv  = rho * Wm1[h] + V * Wm1[HH + h] + 0.5f * bm1[h];
        if (half) utj[nl * UPITCH + h] = uv; else uti[nl * UPITCH + h] = uv;
    }

    // ---- prologue B: W2 as packed bf16 hi/lo, pairs along k ----
    #pragma unroll 1
    for (int idx = tid; idx < 16 * HH; idx += 128) {
        int k2 = idx >> 5, l = idx & 31;
        float w0 = Wm2[(2 * k2) * HH + l];
        float w1 = Wm2[(2 * k2 + 1) * HH + l];
        __nv_bfloat162 h2, l2;
        h2.x = __float2bfloat16_rn(w0);
        h2.y = __float2bfloat16_rn(w1);
        l2.x = __float2bfloat16_rn(w0 - __bfloat162float(h2.x));
        l2.y = __float2bfloat16_rn(w1 - __bfloat162float(h2.y));
        whiP[k2 * WPITCH + l] = *reinterpret_cast<uint32_t*>(&h2);
        wloP[k2 * WPITCH + l] = *reinterpret_cast<uint32_t*>(&l2);
    }
    if (tid < HH) { b2s[tid] = bm2[tid]; w3s[tid] = Wm3[tid]; }
    __syncthreads();

    // ---- hoist B-fragments into registers (loop-invariant across chunks) ----
    uint32_t BH[2][4][2], BL[2][4][2];
    #pragma unroll
    for (int kt = 0; kt < 2; ++kt)
        #pragma unroll
        for (int n = 0; n < 4; ++n) {
            BH[kt][n][0] = whiP[(8*kt + tg)     * WPITCH + 8*n + grp];
            BH[kt][n][1] = whiP[(8*kt + tg + 4) * WPITCH + 8*n + grp];
            BL[kt][n][0] = wloP[(8*kt + tg)     * WPITCH + 8*n + grp];
            BL[kt][n][1] = wloP[(8*kt + tg + 4) * WPITCH + 8*n + grp];
        }

    const float bm3v = bm3[0];
    __nv_bfloat16* qh = qhi_s[wrp];
    __nv_bfloat16* ql = qlo_s[wrp];
    const char* qh_c = (const char*)qh;
    const char* ql_c = (const char*)ql;
    float colacc[4] = {0.f, 0.f, 0.f, 0.f};

    #pragma unroll 1
    for (int c = 0; c < 8; ++c) {
        const int r = (c << 2) + wrp;

        // ---- phase 1: q = lrelu(u_i[r][k] + u_j[jj][k]); split bf16 hi/lo ----
        const float uir = uti[r * UPITCH + lane];      // lane = k
        #pragma unroll 4
        for (int jj = 0; jj < NT; ++jj) {
            float q = lrelu(uir + utj[jj * UPITCH + lane]);
            __nv_bfloat16 h = __float2bfloat16_rn(q);
            __nv_bfloat16 lo = __float2bfloat16_rn(q - __bfloat162float(h));
            qh[jj * QPITCH + lane] = h;                // STS.16, word-merged
            ql[jj * QPITCH + lane] = lo;
        }
        __syncwarp();

        // ---- phase 2: bf16x3 HMMA ----
        float d[2][4][4];
        #pragma unroll
        for (int m = 0; m < 2; ++m)
            #pragma unroll
            for (int n = 0; n < 4; ++n)
                #pragma unroll
                for (int e = 0; e < 4; ++e) d[m][n][e] = 0.f;

        #pragma unroll
        for (int kt = 0; kt < 2; ++kt) {
            uint32_t ah[2][4], al[2][4];
            #pragma unroll
            for (int m = 0; m < 2; ++m) {
                // byte offsets: row*(QPITCH*2) + kt*32 + tg*4 (+16 for k+8 group)
                int r0 = (16*m + grp) * (QPITCH * 2) + kt * 32 + tg * 4;
                int r1 = (16*m + grp + 8) * (QPITCH * 2) + kt * 32 + tg * 4;
                ah[m][0] = *(const uint32_t*)(qh_c + r0);
                ah[m][1] = *(const uint32_t*)(qh_c + r1);
                ah[m][2] = *(const uint32_t*)(qh_c + r0 + 16);
                ah[m][3] = *(const uint32_t*)(qh_c + r1 + 16);
                al[m][0] = *(const uint32_t*)(ql_c + r0);
                al[m][1] = *(const uint32_t*)(ql_c + r1);
                al[m][2] = *(const uint32_t*)(ql_c + r0 + 16);
                al[m][3] = *(const uint32_t*)(ql_c + r1 + 16);
            }
            #pragma unroll
            for (int n = 0; n < 4; ++n)
                #pragma unroll
                for (int m = 0; m < 2; ++m) {
                    MMA_BF16(d[m][n][0], d[m][n][1], d[m][n][2], d[m][n][3],
                             ah[m][0], ah[m][1], ah[m][2], ah[m][3],
                             BH[kt][n][0], BH[kt][n][1]);
                    MMA_BF16(d[m][n][0], d[m][n][1], d[m][n][2], d[m][n][3],
                             ah[m][0], ah[m][1], ah[m][2], ah[m][3],
                             BL[kt][n][0], BL[kt][n][1]);
                    MMA_BF16(d[m][n][0], d[m][n][1], d[m][n][2], d[m][n][3],
                             al[m][0], al[m][1], al[m][2], al[m][3],
                             BH[kt][n][0], BH[kt][n][1]);
                }
        }

        // ---- epilogue: thread owns pairs jj = grp + 8t; cols l = 8n + 2tg(+1) ----
        float me[4];
        #pragma unroll
        for (int t = 0; t < 4; ++t) {
            const int m  = t >> 1;
            const int o0 = (t & 1) << 1;
            float s = 0.f;
            #pragma unroll
            for (int n = 0; n < 4; ++n) {
                int l0 = 8*n + 2*tg;
                s += lrelu(d[m][n][o0]     + b2s[l0])     * w3s[l0];
                s += lrelu(d[m][n][o0 + 1] + b2s[l0 + 1]) * w3s[l0 + 1];
            }
            s += __shfl_xor_sync(0xffffffffu, s, 1);
            s += __shfl_xor_sync(0xffffffffu, s, 2);
            me[t] = tanhf(s + bm3v);
        }

        // ---- row credit ----
        float tr = 0.f;
        if (tg == 0) {
            #pragma unroll
            for (int t = 0; t < 4; ++t)
                tr += A[(size_t)(i0 + r) * NN + j0 + grp + 8*t] * me[t];
        }
        tr += __shfl_xor_sync(0xffffffffu, tr, 1);
        tr += __shfl_xor_sync(0xffffffffu, tr, 2);
        tr += __shfl_xor_sync(0xffffffffu, tr, 4);
        tr += __shfl_xor_sync(0xffffffffu, tr, 8);
        tr += __shfl_xor_sync(0xffffffffu, tr, 16);
        if (lane == 0)
            g_part[(size_t)(b * NTILES + tj) * NN + i0 + r] = tr;

        // ---- col credit (off-diag) ----
        if (!diag) {
            #pragma unroll
            for (int t = 0; t < 4; ++t)
                colacc[t] += A[(size_t)(j0 + grp + 8*t) * NN + i0 + r] * me[t];
        }
        __syncwarp();
    }

    if (!diag) {
        if (tg == 0) {
            #pragma unroll
            for (int t = 0; t < 4; ++t) csh[wrp][grp + 8*t] = colacc[t];
        }
        __syncthreads();
        if (wrp == 0) {
            float cv = csh[0][lane] + csh[1][lane] + csh[2][lane] + csh[3][lane];
            g_part[(size_t)(b * NTILES + ti) * NN + j0 + lane] = cv;
        }
    }
}

// ---------------------------------------------------------------------------
// Kernel 2: finalize — sum 32 partials per node, node MLP.
// ---------------------------------------------------------------------------
__global__ __launch_bounds__(128) void mpnn_finalize(
    const float* __restrict__ x,
    const float* __restrict__ Wx1, const float* __restrict__ bx1,
    const float* __restrict__ Wx2, const float* __restrict__ bx2,
    const float* __restrict__ Wx3, const float* __restrict__ bx3,
    float* __restrict__ out)
{
    __shared__ float hsh[4][HH];
    const int lane = threadIdx.x & 31;
    const int wrp  = threadIdx.x >> 5;
    const int node = blockIdx.x * 4 + wrp;
    const int b    = node >> 10;
    const int i    = node & (NN - 1);

    float ps = g_part[(size_t)(b * NTILES + lane) * NN + i];
    #pragma unroll
    for (int off = 16; off; off >>= 1) ps += __shfl_xor_sync(0xffffffffu, ps, off);
    const float msum = ps;

    const float rho = x[node * 2 + 0];
    float h1b = lrelu(rho * Wx1[lane] + msum * Wx1[HH + lane] + bx1[lane]);
    hsh[wrp][lane] = h1b;
    __syncwarp();

    float h2b = bx2[lane];
    #pragma unroll
    for (int k = 0; k < HH; ++k) h2b += Wx2[k * HH + lane] * hsh[wrp][k];

    float v = lrelu(h2b) * Wx3[lane];
    #pragma unroll
    for (int off = 16; off; off >>= 1) v += __shfl_xor_sync(0xffffffffu, v, off);

    if (lane == 0) out[node] = tanhf(v + bx3[0]);
}

// ---------------------------------------------------------------------------
extern "C" void kernel_launch(void* const* d_in, const int* in_sizes, int n_in,
                              void* d_out, int out_size) {
    const float* x   = (const float*)d_in[0];
    const float* A   = (const float*)d_in[1];
    const float* Wm1 = (const float*)d_in[2];
    const float* bm1 = (const float*)d_in[3];
    const float* Wm2 = (const float*)d_in[4];
    const float* bm2 = (const float*)d_in[5];
    const float* Wm3 = (const float*)d_in[6];
    const float* bm3 = (const float*)d_in[7];
    const float* Wx1 = (const float*)d_in[8];
    const float* bx1 = (const float*)d_in[9];
    const float* Wx2 = (const float*)d_in[10];
    const float* bx2 = (const float*)d_in[11];
    const float* Wx3 = (const float*)d_in[12];
    const float* bx3 = (const float*)d_in[13];
    float* out = (float*)d_out;

    mpnn_pairs<<<BB * NPAIRT, 128>>>(x, A, Wm1, bm1, Wm2, bm2, Wm3, bm3);
    mpnn_finalize<<<BN / 4, 128>>>(x, Wx1, bx1, Wx2, bx2, Wx3, bx3, out);
}